// round 14
// baseline (speedup 1.0000x reference)
#include <cuda_runtime.h>

// RMAC: x[64,2048,16,16] -> out[64, 14*2048], L2-normalized per batch row.
// Regions: 1x(16x16 @0,0) + 4x(10x10 @{0,4}^2) + 9x(8x8 @{0,3,6}^2)
// Single launch: blocks [0,4096) pool; blocks [4096,4544) per-batch norm,
// released by per-batch arrival counters (no gridsync, no second launch).

#define BATCH 64
#define CH    2048
#define NREG  14
#define OUTB  (NREG * CH)          // 28672
#define PLANES (BATCH * CH)        // 131072
#define PPB   32                   // planes per pool block (4 per warp, 8 warps)
#define NBLK  (PLANES / PPB)       // 4096 pool blocks
#define TPB   (NBLK / BATCH)       // 64 pool blocks per batch
#define NNRM  448                  // norm blocks (7 per batch)
#define NPB   (NNRM / BATCH)       // 7
#define CSTR  20                   // cut-column row stride (floats)
#define PSTR  160                  // plane stride = 8 cuts * CSTR

__device__ float g_part[NBLK];             // per-block partial sum-of-squares
__device__ int   g_arrive[BATCH];          // pool-block arrival counters
__device__ int   g_done[BATCH];            // norm-block completion counters

__global__ __launch_bounds__(256) void rmac_all(const float* __restrict__ x,
                                                float* __restrict__ out) {
    __shared__ float S[PPB * PSTR];      // 20 KB: [plane][cut][row] cut prefixes
    __shared__ float sval[NREG * 33];    // staged outputs [region][plane]
    __shared__ float wsq[8];

    const int t    = threadIdx.x;

    if (blockIdx.x >= NBLK) {
        // ================= NORM PATH (448 trailing blocks) =================
        const int nb = blockIdx.x - NBLK;       // 0..447
        const int b  = nb / NPB;                // batch
        __shared__ float ws[2];
        __shared__ float sscale;

        // Wait for this batch's 64 pool blocks (t0 spins; rest park at barrier)
        if (t == 0) {
            volatile int* arr = &g_arrive[b];
            while (*arr != TPB) { __nanosleep(128); }
            __threadfence();                    // acquire
        }
        __syncthreads();

        // out loads (in flight while we reduce the partials)
        float4* o4 = (float4*)out;
        const int base = nb * 1024 + t;         // 1024 float4 per norm block
        float4 v0 = o4[base];
        float4 v1 = o4[base + 256];
        float4 v2 = o4[base + 512];
        float4 v3 = o4[base + 768];

        // Batch scale: fixed-order deterministic reduce of 64 partials
        float s = (t < TPB) ? g_part[b * TPB + t] : 0.f;
        #pragma unroll
        for (int o = 16; o; o >>= 1) s += __shfl_xor_sync(0xffffffffu, s, o);
        if (t < TPB && (t & 31) == 0) ws[t >> 5] = s;
        __syncthreads();
        if (t == 0) sscale = 1.f / fmaxf(sqrtf(ws[0] + ws[1]), 1e-12f);
        __syncthreads();
        const float sc = sscale;

        v0.x *= sc; v0.y *= sc; v0.z *= sc; v0.w *= sc;
        v1.x *= sc; v1.y *= sc; v1.z *= sc; v1.w *= sc;
        v2.x *= sc; v2.y *= sc; v2.z *= sc; v2.w *= sc;
        v3.x *= sc; v3.y *= sc; v3.z *= sc; v3.w *= sc;
        o4[base]       = v0;
        o4[base + 256] = v1;
        o4[base + 512] = v2;
        o4[base + 768] = v3;

        // Reset per-batch state for the next graph replay (last of 7 blocks)
        __syncthreads();
        if (t == 0) {
            int od = atomicAdd(&g_done[b], 1);
            if (od == NPB - 1) { g_arrive[b] = 0; g_done[b] = 0; }
        }
        return;
    }

    // ================== POOL PATH (blocks 0..4095) ==================
    const int w    = t >> 5;
    const int lane = t & 31;
    const int tile = blockIdx.x;
    const int pb   = tile * PPB;         // 32 | 2048 -> block stays in one batch
    const int b    = pb >> 11;
    const int c0   = pb & 2047;

    // ---- Coalesced load: warp covers 4 planes = 256 float4, 8 per lane ----
    const float4* xw = (const float4*)(x + (size_t)(pb + w * 4) * 256);
    float4 f[8];
    #pragma unroll
    for (int k = 0; k < 8; ++k) f[k] = __ldcs(xw + 32 * k + lane);

    // ---- Phase 1: per float4 chunk, horizontal prefix cuts via 4-lane scan ----
    // f[k] = quarter (lane&3) of row 8*(k&1)+(lane>>2) of plane (k>>1).
    // Cuts per quarter q: (2q, 2q+1) = (p3,p4)|(p6,p8)|(p10,p11)|(p14,p16).
    const int q      = lane & 3;
    const int rowoff = lane >> 2;
    #pragma unroll
    for (int k = 0; k < 8; ++k) {
        float xv = f[k].x, yv = f[k].y, zv = f[k].z, wv = f[k].w;
        float txy = xv + yv;
        float qs  = txy + zv + wv;
        float incl = qs;
        float s1 = __shfl_up_sync(0xffffffffu, incl, 1, 4);
        if (q >= 1) incl += s1;
        float s2 = __shfl_up_sync(0xffffffffu, incl, 2, 4);
        if (q >= 2) incl += s2;
        float Ex = incl - qs;
        float pa = Ex + txy + ((q == 0) ? zv : 0.f);       // p3|p6|p10|p14
        float pc = (q == 2) ? (Ex + txy + zv) : (Ex + qs); // p4|p8|p11|p16
        int lp  = w * 4 + (k >> 1);
        int row = 8 * (k & 1) + rowoff;
        S[lp * PSTR + (2 * q)     * CSTR + row] = pa;
        S[lp * PSTR + (2 * q + 1) * CSTR + row] = pc;
    }
    __syncwarp();

    // ---- Phase 2: lane = (plane pp, cut k2). Vertical prefix of one cut column.
    const int pp = lane >> 3;
    const int k2 = lane & 7;
    const float* col = &S[(w * 4 + pp) * PSTR + k2 * CSTR];
    float4 r0 = *(const float4*)(col + 0);
    float4 r1 = *(const float4*)(col + 4);
    float4 r2 = *(const float4*)(col + 8);
    float4 r3 = *(const float4*)(col + 12);
    float P[16];
    P[0]  = r0.x;          P[1]  = P[0]  + r0.y;  P[2]  = P[1]  + r0.z;  P[3]  = P[2]  + r0.w;
    P[4]  = P[3]  + r1.x;  P[5]  = P[4]  + r1.y;  P[6]  = P[5]  + r1.z;  P[7]  = P[6]  + r1.w;
    P[8]  = P[7]  + r2.x;  P[9]  = P[8]  + r2.y;  P[10] = P[9]  + r2.z;  P[11] = P[10] + r2.w;
    P[12] = P[11] + r3.x;  P[13] = P[12] + r3.y;  P[14] = P[13] + r3.z;  P[15] = P[14] + r3.w;

    float A  = P[9];            // rows [0,10)
    float B  = P[13] - P[3];    // rows [4,14)
    float C  = P[7];            // rows [0,8)
    float D  = P[10] - P[2];    // rows [3,11)
    float E2 = P[13] - P[5];    // rows [6,14)
    float F  = P[15];           // rows [0,16)

    // Exchange: minuend lanes fetch subtrahend columns (k-5 and k-4 mod 8 in-group)
    const int gbase = lane & ~7;
    const int src5  = gbase | ((k2 + 3) & 7);   // k-5 mod 8
    const int src4  = gbase | ((k2 + 4) & 7);   // k-4 mod 8
    float rA5 = __shfl_sync(0xffffffffu, A,  src5);
    float rB5 = __shfl_sync(0xffffffffu, B,  src5);
    float rC5 = __shfl_sync(0xffffffffu, C,  src5);
    float rD5 = __shfl_sync(0xffffffffu, D,  src5);
    float rE5 = __shfl_sync(0xffffffffu, E2, src5);
    float rC4 = __shfl_sync(0xffffffffu, C,  src4);
    float rD4 = __shfl_sync(0xffffffffu, D,  src4);
    float rE4 = __shfl_sync(0xffffffffu, E2, src4);

    // Cut ids: c0=p3 c1=p4 c2=p6 c3=p8 c4=p10 c5=p11 c6=p14 c7=p16
    // h1=c4 h2=c6-c1 h3=c3 h4=c5-c0 h5=c6-c2 h0=c7
    const int lp2 = w * 4 + pp;
    float sq = 0.f;
    if (k2 == 7) {
        float v0 = F * (1.f / 256.f);
        sval[0 * 33 + lp2] = v0;
        sq = v0 * v0;
    } else if (k2 == 4) {
        float v1 = A * 0.01f;                    // r1
        float v3 = B * 0.01f;                    // r3
        sval[1 * 33 + lp2] = v1;
        sval[3 * 33 + lp2] = v3;
        sq = v1 * v1 + v3 * v3;
    } else if (k2 == 6) {
        float v2  = (A  - rA5) * 0.01f;          // r2  (c6-c1)
        float v4  = (B  - rB5) * 0.01f;          // r4
        float v7  = (C  - rC4) * (1.f / 64.f);   // r7  (c6-c2)
        float v10 = (D  - rD4) * (1.f / 64.f);   // r10
        float v13 = (E2 - rE4) * (1.f / 64.f);   // r13
        sval[2  * 33 + lp2] = v2;
        sval[4  * 33 + lp2] = v4;
        sval[7  * 33 + lp2] = v7;
        sval[10 * 33 + lp2] = v10;
        sval[13 * 33 + lp2] = v13;
        sq = v2 * v2 + v4 * v4 + v7 * v7 + v10 * v10 + v13 * v13;
    } else if (k2 == 5) {
        float v6  = (C  - rC5) * (1.f / 64.f);   // r6  (c5-c0)
        float v9  = (D  - rD5) * (1.f / 64.f);   // r9
        float v12 = (E2 - rE5) * (1.f / 64.f);   // r12
        sval[6  * 33 + lp2] = v6;
        sval[9  * 33 + lp2] = v9;
        sval[12 * 33 + lp2] = v12;
        sq = v6 * v6 + v9 * v9 + v12 * v12;
    } else if (k2 == 3) {
        float v5  = C  * (1.f / 64.f);           // r5
        float v8  = D  * (1.f / 64.f);           // r8
        float v11 = E2 * (1.f / 64.f);           // r11
        sval[5  * 33 + lp2] = v5;
        sval[8  * 33 + lp2] = v8;
        sval[11 * 33 + lp2] = v11;
        sq = v5 * v5 + v8 * v8 + v11 * v11;
    }

    // ---- Sum of squares: warp butterfly -> block partial ----
    #pragma unroll
    for (int o = 16; o; o >>= 1) sq += __shfl_xor_sync(0xffffffffu, sq, o);
    if (lane == 0) wsq[w] = sq;
    __syncthreads();
    if (t == 0) {
        float tot = 0.f;
        #pragma unroll
        for (int i = 0; i < 8; ++i) tot += wsq[i];
        g_part[tile] = tot;
    }

    // ---- Coalesced store: 14 regions x 32 planes = 448 elems ----
    #pragma unroll
    for (int i = t; i < NREG * PPB; i += 256) {
        int rr = i >> 5, p = i & 31;
        out[(size_t)b * OUTB + rr * CH + c0 + p] = sval[rr * 33 + p];
    }

    // ---- Release: out + g_part visible, then bump this batch's counter ----
    __syncthreads();
    if (t == 0) {
        __threadfence();
        atomicAdd(&g_arrive[b], 1);
    }
}

extern "C" void kernel_launch(void* const* d_in, const int* in_sizes, int n_in,
                              void* d_out, int out_size) {
    const float* x = (const float*)d_in[0];
    float* out = (float*)d_out;
    rmac_all<<<NBLK + NNRM, 256>>>(x, out);   // 4544 blocks, one launch
}

// round 15
// speedup vs baseline: 1.0702x; 1.0702x over previous
#include <cuda_runtime.h>

// RMAC: x[64,2048,16,16] -> out[64, 14*2048], L2-normalized per batch row.
// Regions: 1x(16x16 @0,0) + 4x(10x10 @{0,4}^2) + 9x(8x8 @{0,3,6}^2)
// Champion 2-kernel shape; x loads use DEFAULT caching (L2-retaining across
// graph replays; x=134MB vs L2=126MB).

#define BATCH 64
#define CH    2048
#define NREG  14
#define OUTB  (NREG * CH)          // 28672
#define PLANES (BATCH * CH)        // 131072
#define PPB   32                   // planes per block (4 per warp, 8 warps)
#define NBLK  (PLANES / PPB)       // 4096
#define TPB   (NBLK / BATCH)       // 64 pool blocks per batch
#define CSTR  20                   // cut-column row stride (floats)
#define PSTR  160                  // plane stride = 8 cuts * CSTR

__device__ float g_part[NBLK];     // per-block partial sum-of-squares

__global__ __launch_bounds__(256) void rmac_pool(const float* __restrict__ x,
                                                 float* __restrict__ out) {
    __shared__ float S[PPB * PSTR];      // 20 KB: [plane][cut][row] cut prefixes
    __shared__ float sval[NREG * 33];    // staged outputs [region][plane]
    __shared__ float wsq[8];

    const int t    = threadIdx.x;
    const int w    = t >> 5;
    const int lane = t & 31;
    const int tile = blockIdx.x;
    const int pb   = tile * PPB;         // 32 | 2048 -> block stays in one batch
    const int b    = pb >> 11;
    const int c0   = pb & 2047;

    // ---- Coalesced load (default caching -> L2-retaining across replays) ----
    const float4* xw = (const float4*)(x + (size_t)(pb + w * 4) * 256);
    float4 f[8];
    #pragma unroll
    for (int k = 0; k < 8; ++k) f[k] = xw[32 * k + lane];

    // ---- Phase 1: per float4 chunk, horizontal prefix cuts via 4-lane scan ----
    // f[k] = quarter (lane&3) of row 8*(k&1)+(lane>>2) of plane (k>>1).
    // Cuts per quarter q: (2q, 2q+1) = (p3,p4)|(p6,p8)|(p10,p11)|(p14,p16).
    const int q      = lane & 3;
    const int rowoff = lane >> 2;
    #pragma unroll
    for (int k = 0; k < 8; ++k) {
        float xv = f[k].x, yv = f[k].y, zv = f[k].z, wv = f[k].w;
        float txy = xv + yv;
        float qs  = txy + zv + wv;
        float incl = qs;
        float s1 = __shfl_up_sync(0xffffffffu, incl, 1, 4);
        if (q >= 1) incl += s1;
        float s2 = __shfl_up_sync(0xffffffffu, incl, 2, 4);
        if (q >= 2) incl += s2;
        float Ex = incl - qs;
        float pa = Ex + txy + ((q == 0) ? zv : 0.f);       // p3|p6|p10|p14
        float pc = (q == 2) ? (Ex + txy + zv) : (Ex + qs); // p4|p8|p11|p16
        int lp  = w * 4 + (k >> 1);
        int row = 8 * (k & 1) + rowoff;
        S[lp * PSTR + (2 * q)     * CSTR + row] = pa;
        S[lp * PSTR + (2 * q + 1) * CSTR + row] = pc;
    }
    __syncwarp();

    // ---- Phase 2: lane = (plane pp, cut k2). Vertical prefix of one cut column.
    const int pp = lane >> 3;
    const int k2 = lane & 7;
    const float* col = &S[(w * 4 + pp) * PSTR + k2 * CSTR];
    float4 r0 = *(const float4*)(col + 0);
    float4 r1 = *(const float4*)(col + 4);
    float4 r2 = *(const float4*)(col + 8);
    float4 r3 = *(const float4*)(col + 12);
    float P[16];
    P[0]  = r0.x;          P[1]  = P[0]  + r0.y;  P[2]  = P[1]  + r0.z;  P[3]  = P[2]  + r0.w;
    P[4]  = P[3]  + r1.x;  P[5]  = P[4]  + r1.y;  P[6]  = P[5]  + r1.z;  P[7]  = P[6]  + r1.w;
    P[8]  = P[7]  + r2.x;  P[9]  = P[8]  + r2.y;  P[10] = P[9]  + r2.z;  P[11] = P[10] + r2.w;
    P[12] = P[11] + r3.x;  P[13] = P[12] + r3.y;  P[14] = P[13] + r3.z;  P[15] = P[14] + r3.w;

    float A  = P[9];            // rows [0,10)
    float B  = P[13] - P[3];    // rows [4,14)
    float C  = P[7];            // rows [0,8)
    float D  = P[10] - P[2];    // rows [3,11)
    float E2 = P[13] - P[5];    // rows [6,14)
    float F  = P[15];           // rows [0,16)

    // Exchange: minuend lanes fetch subtrahend columns (k-5 and k-4 mod 8 in-group)
    const int gbase = lane & ~7;
    const int src5  = gbase | ((k2 + 3) & 7);   // k-5 mod 8
    const int src4  = gbase | ((k2 + 4) & 7);   // k-4 mod 8
    float rA5 = __shfl_sync(0xffffffffu, A,  src5);
    float rB5 = __shfl_sync(0xffffffffu, B,  src5);
    float rC5 = __shfl_sync(0xffffffffu, C,  src5);
    float rD5 = __shfl_sync(0xffffffffu, D,  src5);
    float rE5 = __shfl_sync(0xffffffffu, E2, src5);
    float rC4 = __shfl_sync(0xffffffffu, C,  src4);
    float rD4 = __shfl_sync(0xffffffffu, D,  src4);
    float rE4 = __shfl_sync(0xffffffffu, E2, src4);

    // Cut ids: c0=p3 c1=p4 c2=p6 c3=p8 c4=p10 c5=p11 c6=p14 c7=p16
    // h1=c4 h2=c6-c1 h3=c3 h4=c5-c0 h5=c6-c2 h0=c7
    const int lp2 = w * 4 + pp;
    float sq = 0.f;
    if (k2 == 7) {
        float v0 = F * (1.f / 256.f);
        sval[0 * 33 + lp2] = v0;
        sq = v0 * v0;
    } else if (k2 == 4) {
        float v1 = A * 0.01f;                    // r1
        float v3 = B * 0.01f;                    // r3
        sval[1 * 33 + lp2] = v1;
        sval[3 * 33 + lp2] = v3;
        sq = v1 * v1 + v3 * v3;
    } else if (k2 == 6) {
        float v2  = (A  - rA5) * 0.01f;          // r2  (c6-c1)
        float v4  = (B  - rB5) * 0.01f;          // r4
        float v7  = (C  - rC4) * (1.f / 64.f);   // r7  (c6-c2)
        float v10 = (D  - rD4) * (1.f / 64.f);   // r10
        float v13 = (E2 - rE4) * (1.f / 64.f);   // r13
        sval[2  * 33 + lp2] = v2;
        sval[4  * 33 + lp2] = v4;
        sval[7  * 33 + lp2] = v7;
        sval[10 * 33 + lp2] = v10;
        sval[13 * 33 + lp2] = v13;
        sq = v2 * v2 + v4 * v4 + v7 * v7 + v10 * v10 + v13 * v13;
    } else if (k2 == 5) {
        float v6  = (C  - rC5) * (1.f / 64.f);   // r6  (c5-c0)
        float v9  = (D  - rD5) * (1.f / 64.f);   // r9
        float v12 = (E2 - rE5) * (1.f / 64.f);   // r12
        sval[6  * 33 + lp2] = v6;
        sval[9  * 33 + lp2] = v9;
        sval[12 * 33 + lp2] = v12;
        sq = v6 * v6 + v9 * v9 + v12 * v12;
    } else if (k2 == 3) {
        float v5  = C  * (1.f / 64.f);           // r5
        float v8  = D  * (1.f / 64.f);           // r8
        float v11 = E2 * (1.f / 64.f);           // r11
        sval[5  * 33 + lp2] = v5;
        sval[8  * 33 + lp2] = v8;
        sval[11 * 33 + lp2] = v11;
        sq = v5 * v5 + v8 * v8 + v11 * v11;
    }

    // ---- Sum of squares: warp butterfly -> block -> per-block partial ----
    #pragma unroll
    for (int o = 16; o; o >>= 1) sq += __shfl_xor_sync(0xffffffffu, sq, o);
    if (lane == 0) wsq[w] = sq;
    __syncthreads();
    if (t == 0) {
        float tot = 0.f;
        #pragma unroll
        for (int i = 0; i < 8; ++i) tot += wsq[i];
        g_part[tile] = tot;
    }

    // ---- Coalesced store: 14 regions x 32 planes = 448 elems ----
    #pragma unroll
    for (int i = t; i < NREG * PPB; i += 256) {
        int rr = i >> 5, p = i & 31;
        out[(size_t)b * OUTB + rr * CH + c0 + p] = sval[rr * 33 + p];
    }
}

// 448 blocks x 256 threads x 4 float4. Each block redundantly computes its
// batch's scale: coalesced 64-lane g_part load + butterfly (fixed order,
// deterministic), overlapped with the hoisted out loads.
__global__ __launch_bounds__(256) void rmac_norm(float* __restrict__ out) {
    __shared__ float ws[2];
    __shared__ float sscale;
    const int t = threadIdx.x;
    const int b = blockIdx.x / 7;          // 1024 float4 per block; 7168 per batch

#if __CUDA_ARCH__ >= 900
    cudaGridDependencySynchronize();       // pool complete -> out + g_part final
#endif

    // Hoist the out loads: issue before the reduce so latency overlaps it.
    float4* o4 = (float4*)out;
    const int base = blockIdx.x * 1024 + t;
    float4 v0 = o4[base];
    float4 v1 = o4[base + 256];
    float4 v2 = o4[base + 512];
    float4 v3 = o4[base + 768];

    // Batch scale: warps 0,1 reduce the 64 partials.
    float s = (t < TPB) ? g_part[b * TPB + t] : 0.f;
    #pragma unroll
    for (int o = 16; o; o >>= 1) s += __shfl_xor_sync(0xffffffffu, s, o);
    if (t < TPB && (t & 31) == 0) ws[t >> 5] = s;
    __syncthreads();
    if (t == 0) sscale = 1.f / fmaxf(sqrtf(ws[0] + ws[1]), 1e-12f);
    __syncthreads();
    const float sc = sscale;

    v0.x *= sc; v0.y *= sc; v0.z *= sc; v0.w *= sc;
    v1.x *= sc; v1.y *= sc; v1.z *= sc; v1.w *= sc;
    v2.x *= sc; v2.y *= sc; v2.z *= sc; v2.w *= sc;
    v3.x *= sc; v3.y *= sc; v3.z *= sc; v3.w *= sc;
    o4[base]       = v0;
    o4[base + 256] = v1;
    o4[base + 512] = v2;
    o4[base + 768] = v3;
}

extern "C" void kernel_launch(void* const* d_in, const int* in_sizes, int n_in,
                              void* d_out, int out_size) {
    const float* x = (const float*)d_in[0];
    float* out = (float*)d_out;

    rmac_pool<<<NBLK, 256>>>(x, out);       // 4096 blocks (champion shape)

    cudaLaunchConfig_t cfg = {};
    cfg.gridDim  = dim3(448);
    cfg.blockDim = dim3(256);
    cudaLaunchAttribute attrs[1];
    attrs[0].id = cudaLaunchAttributeProgrammaticStreamSerialization;
    attrs[0].val.programmaticStreamSerializationAllowed = 1;
    cfg.attrs = attrs;
    cfg.numAttrs = 1;
    void* nargs[] = {(void*)&out};
    cudaLaunchKernelExC(&cfg, (void*)rmac_norm, nargs);
}